// round 9
// baseline (speedup 1.0000x reference)
#include <cuda_runtime.h>
#include <cuda_bf16.h>
#include <math.h>
#include <stdint.h>

// ---------------------------------------------------------------- constants
#define BB    16
#define NPTS1 1024
#define NPTS2 4096
#define CF    512
#define EPSI  1e-10f

#define MTILES1 128            // 16384/128
#define MTILES2 512            // 65536/128
#define KITERS  16             // 512 / BK32

// SMEM tile geometry: per matrix 128 rows x 32 bf16 (64B data, padded to 80B)
#define ROW_STRIDE 80
#define MAT_BYTES  (128 * ROW_STRIDE)      // 10240
#define STAGE_BYTES (4 * MAT_BYTES)        // 40960 (Ahi|Alo|Bhi|Blo)
#define NSTAGES 2
#define SMEM_GEMM   (NSTAGES * STAGE_BYTES)  // 81920  -> 2 CTAs/SM

// ---------------------------------------------------------------- scratch
__device__ __align__(128) __nv_bfloat16 g_fA_hi[16384 * 512];
__device__ __align__(128) __nv_bfloat16 g_fA_lo[16384 * 512];
__device__ __align__(128) __nv_bfloat16 g_w1_hi[512 * 512];
__device__ __align__(128) __nv_bfloat16 g_w1_lo[512 * 512];
__device__ __align__(128) __nv_bfloat16 g_w2_hi[512 * 512];
__device__ __align__(128) __nv_bfloat16 g_w2_lo[512 * 512];
__device__ __align__(128) __nv_bfloat16 g_a2_hi[65536 * 512];
__device__ __align__(128) __nv_bfloat16 g_a2_lo[65536 * 512];
__device__ float g_gbuf[16384 * 512];   // GEMM1 output (fp32)

// ---------------------------------------------------------------- helpers
__device__ __forceinline__ uint32_t smem_u32(const void* p) {
    uint32_t a;
    asm("{ .reg .u64 t; cvta.to.shared.u64 t, %1; cvt.u32.u64 %0, t; }"
        : "=r"(a) : "l"(p));
    return a;
}

__device__ __forceinline__ void cp16(uint32_t dst, const void* src) {
    asm volatile("cp.async.cg.shared.global [%0], [%1], 16;" :: "r"(dst), "l"(src));
}

#define CP_COMMIT()  asm volatile("cp.async.commit_group;" ::: "memory")
#define CP_WAIT1()   asm volatile("cp.async.wait_group 1;" ::: "memory")
#define CP_WAIT0()   asm volatile("cp.async.wait_group 0;" ::: "memory")

#define LDSM_X4(r0_, r1_, r2_, r3_, addr_)                                    \
    asm volatile("ldmatrix.sync.aligned.m8n8.x4.shared.b16 {%0,%1,%2,%3}, [%4];" \
        : "=r"(r0_), "=r"(r1_), "=r"(r2_), "=r"(r3_) : "r"(addr_))

// D += A(16x16 bf16, row-major) * B(16x8 bf16, col-major), fp32 accum
#define MMA_BF16(d, a, b0_, b1_)                                              \
    asm volatile("mma.sync.aligned.m16n8k16.row.col.f32.bf16.bf16.f32 "       \
        "{%0,%1,%2,%3}, {%4,%5,%6,%7}, {%8,%9}, {%0,%1,%2,%3};"               \
        : "+f"((d)[0]), "+f"((d)[1]), "+f"((d)[2]), "+f"((d)[3])              \
        : "r"((a)[0]), "r"((a)[1]), "r"((a)[2]), "r"((a)[3]),                 \
          "r"(b0_), "r"(b1_))

// ---------------------------------------------------------------- converters
template <int WHICH>  // 0: feat->fA   1: W1->w1   2: W2->w2
__global__ __launch_bounds__(256) void convert_split_kernel(const float* __restrict__ src)
{
    __nv_bfloat16* dhi = (WHICH == 0) ? g_fA_hi : (WHICH == 1) ? g_w1_hi : g_w2_hi;
    __nv_bfloat16* dlo = (WHICH == 0) ? g_fA_lo : (WHICH == 1) ? g_w1_lo : g_w2_lo;

    const long t = (long)blockIdx.x * 256 + threadIdx.x;
    const float4* s = (const float4*)(src + t * 8);
    float4 v0 = s[0], v1 = s[1];
    float v[8] = { v0.x, v0.y, v0.z, v0.w, v1.x, v1.y, v1.z, v1.w };

    union { __nv_bfloat16 h[8]; uint4 u; } H, L;
#pragma unroll
    for (int k = 0; k < 8; k++) {
        H.h[k] = __float2bfloat16(v[k]);
        L.h[k] = __float2bfloat16(v[k] - __bfloat162float(H.h[k]));
    }
    *(uint4*)(dhi + t * 8) = H.u;
    *(uint4*)(dlo + t * 8) = L.u;
}

// ---------------------------------------------------------------- MMA GEMM
// C[M,512] = A[M,512] @ W[512,512]^T + bias, 3-term bf16 split:
//   AhiBhi + AhiBlo + AloBhi  (AloBlo dropped, ~2^-18)
// 128 threads, 4 warps in 2x2; warp tile 64x64 (4 m-tiles x 8 n-tiles).
// MODE 0: A = fA (feat), B = w1, C = g_gbuf.  MODE 1: A = a2, B = w2, C = param.
template <int MODE>
__global__ __launch_bounds__(128, 2) void mma_gemm_kernel(const float* __restrict__ bias,
                                                          float* __restrict__ Cout)
{
    extern __shared__ __align__(128) char smem[];
    const uint32_t sbase = smem_u32(smem);

    const int tid  = threadIdx.x;
    const int wid  = tid >> 5, lane = tid & 31;
    const int warp_m = wid & 1;     // 0..1 -> 64-row strip
    const int warp_n = wid >> 1;    // 0..1 -> 64-col strip
    const int qid = lane >> 2;      // lane/4
    const int qtr = lane & 3;       // lane%4
    const int ntile = blockIdx.x, mtile = blockIdx.y;

    const __nv_bfloat16* Ahi = (MODE == 0) ? g_fA_hi : g_a2_hi;
    const __nv_bfloat16* Alo = (MODE == 0) ? g_fA_lo : g_a2_lo;
    const __nv_bfloat16* Bhi = (MODE == 0) ? g_w1_hi : g_w2_hi;
    const __nv_bfloat16* Blo = (MODE == 0) ? g_w1_lo : g_w2_lo;

    const char* gbase[4];
    gbase[0] = (const char*)(Ahi + (long)mtile * 128 * 512);
    gbase[1] = (const char*)(Alo + (long)mtile * 128 * 512);
    gbase[2] = (const char*)(Bhi + (long)ntile * 128 * 512);
    gbase[3] = (const char*)(Blo + (long)ntile * 128 * 512);

    float acc[4][8][4];
#pragma unroll
    for (int mt = 0; mt < 4; mt++)
#pragma unroll
        for (int nt = 0; nt < 8; nt++)
#pragma unroll
            for (int i = 0; i < 4; i++) acc[mt][nt][i] = 0.f;

    // per-lane ldmatrix source offsets (within a matrix tile)
    const uint32_t lrow = lane & 15;            // row within 16-row group
    const uint32_t lcolB = (lane >> 4) * 16;    // 0 or 16 bytes (k-half)
    uint32_t aoff[4], boff[4];
#pragma unroll
    for (int mt = 0; mt < 4; mt++)
        aoff[mt] = (warp_m * 64 + mt * 16 + lrow) * ROW_STRIDE + lcolB;
#pragma unroll
    for (int ntp = 0; ntp < 4; ntp++)
        boff[ntp] = (warp_n * 64 + ntp * 16 + lrow) * ROW_STRIDE + lcolB;

    auto prefetch = [&](int kc, int stage) {
        const uint32_t stg = sbase + stage * STAGE_BYTES;
#pragma unroll
        for (int it = 0; it < 16; it++) {
            const int mat = it >> 2;                      // compile-time
            const int rem = ((it & 3) << 7) + tid;        // 0..511
            const int row = rem >> 2, chk = rem & 3;
            cp16(stg + mat * MAT_BYTES + row * ROW_STRIDE + chk * 16,
                 gbase[mat] + (long)row * 1024 + kc * 64 + chk * 16);
        }
    };

    auto compute = [&](int stage) {
        const uint32_t aHiB = sbase + stage * STAGE_BYTES;
        const uint32_t aLoB = aHiB + MAT_BYTES;
        const uint32_t bHiB = aHiB + 2 * MAT_BYTES;
        const uint32_t bLoB = aHiB + 3 * MAT_BYTES;
#pragma unroll
        for (int ks = 0; ks < 2; ks++) {
            const uint32_t ko = ks * 32;
            // A fragments: 4 m-tiles x hi/lo (8 ldmatrix.x4), reused for 96 MMAs
            uint32_t ah[4][4], al[4][4];
#pragma unroll
            for (int mt = 0; mt < 4; mt++) {
                LDSM_X4(ah[mt][0], ah[mt][1], ah[mt][2], ah[mt][3], aHiB + aoff[mt] + ko);
                LDSM_X4(al[mt][0], al[mt][1], al[mt][2], al[mt][3], aLoB + aoff[mt] + ko);
            }
            // B in two halves of 32 cols to cap live registers
#pragma unroll
            for (int half = 0; half < 2; half++) {
                uint32_t bh[2][4], bl[2][4];
#pragma unroll
                for (int p = 0; p < 2; p++) {
                    const int ntp = half * 2 + p;
                    LDSM_X4(bh[p][0], bh[p][1], bh[p][2], bh[p][3], bHiB + boff[ntp] + ko);
                    LDSM_X4(bl[p][0], bl[p][1], bl[p][2], bl[p][3], bLoB + boff[ntp] + ko);
                }
                // term 1: Ahi * Bhi  (16 MMAs)
#pragma unroll
                for (int p = 0; p < 2; p++) {
                    const int nt0 = (half * 2 + p) * 2;
#pragma unroll
                    for (int mt = 0; mt < 4; mt++) {
                        MMA_BF16(acc[mt][nt0],     ah[mt], bh[p][0], bh[p][2]);
                        MMA_BF16(acc[mt][nt0 + 1], ah[mt], bh[p][1], bh[p][3]);
                    }
                }
                // term 2: Ahi * Blo
#pragma unroll
                for (int p = 0; p < 2; p++) {
                    const int nt0 = (half * 2 + p) * 2;
#pragma unroll
                    for (int mt = 0; mt < 4; mt++) {
                        MMA_BF16(acc[mt][nt0],     ah[mt], bl[p][0], bl[p][2]);
                        MMA_BF16(acc[mt][nt0 + 1], ah[mt], bl[p][1], bl[p][3]);
                    }
                }
                // term 3: Alo * Bhi
#pragma unroll
                for (int p = 0; p < 2; p++) {
                    const int nt0 = (half * 2 + p) * 2;
#pragma unroll
                    for (int mt = 0; mt < 4; mt++) {
                        MMA_BF16(acc[mt][nt0],     al[mt], bh[p][0], bh[p][2]);
                        MMA_BF16(acc[mt][nt0 + 1], al[mt], bh[p][1], bh[p][3]);
                    }
                }
            }
        }
    };

    // 2-stage pipeline (two syncs per iter; prefetch target was consumed
    // in iter kt-1, trailing sync protects it)
    prefetch(0, 0);
    CP_COMMIT();
    for (int kt = 0; kt < KITERS; kt++) {
        if (kt + 1 < KITERS) {
            prefetch(kt + 1, (kt + 1) & 1);
            CP_COMMIT();
            CP_WAIT1();
        } else {
            CP_WAIT0();
        }
        __syncthreads();
        compute(kt & 1);
        __syncthreads();
    }

    // ---- epilogue: +bias, direct float2 stores
    float* Cbase = (MODE == 0) ? g_gbuf : Cout;
#pragma unroll
    for (int nt = 0; nt < 8; nt++) {
        const int col = ntile * 128 + warp_n * 64 + nt * 8 + qtr * 2;
        const float b0 = __ldg(&bias[col]), b1 = __ldg(&bias[col + 1]);
#pragma unroll
        for (int mt = 0; mt < 4; mt++) {
            const int r0 = mtile * 128 + warp_m * 64 + mt * 16 + qid;
            float2 v0, v1;
            v0.x = acc[mt][nt][0] + b0; v0.y = acc[mt][nt][1] + b1;
            v1.x = acc[mt][nt][2] + b0; v1.y = acc[mt][nt][3] + b1;
            *(float2*)&Cbase[(long)r0 * 512 + col] = v0;
            *(float2*)&Cbase[(long)(r0 + 8) * 512 + col] = v1;
        }
    }
}

// ---------------------------------------------------------------- KNN + interp
__global__ __launch_bounds__(256) void knn_interp_relu_kernel(
    const float* __restrict__ xyz_dense, const float* __restrict__ xyz_sparse)
{
    __shared__ float sx[NPTS1], sy[NPTS1], sz[NPTS1];
    __shared__ float sw[128][3];
    __shared__ int   si[128][3];

    const int b  = blockIdx.y;
    const int p0 = blockIdx.x * 128;

    const float* xs = xyz_sparse + (long)b * NPTS1 * 3;
    for (int i = threadIdx.x; i < NPTS1; i += 256) {
        sx[i] = xs[i * 3 + 0];
        sy[i] = xs[i * 3 + 1];
        sz[i] = xs[i * 3 + 2];
    }
    __syncthreads();

    if (threadIdx.x < 128) {
        const int p = p0 + threadIdx.x;
        const float* xd = xyz_dense + ((long)b * NPTS2 + p) * 3;
        const float px = xd[0], py = xd[1], pz = xd[2];

        float d0 = 1e30f, d1 = 1e30f, d2 = 1e30f;
        int   i0 = 0, i1 = 0, i2 = 0;
#pragma unroll 4
        for (int j = 0; j < NPTS1; j++) {
            float dx = px - sx[j], dy = py - sy[j], dz = pz - sz[j];
            float d = dx * dx + dy * dy + dz * dz;
            if (d < d0)      { d2 = d1; i2 = i1; d1 = d0; i1 = i0; d0 = d; i0 = j; }
            else if (d < d1) { d2 = d1; i2 = i1; d1 = d;  i1 = j; }
            else if (d < d2) { d2 = d;  i2 = j; }
        }
        float w0 = 1.f / (sqrtf(d0) + EPSI);
        float w1 = 1.f / (sqrtf(d1) + EPSI);
        float w2 = 1.f / (sqrtf(d2) + EPSI);
        const float inv = 1.f / (w0 + w1 + w2);
        sw[threadIdx.x][0] = w0 * inv;
        sw[threadIdx.x][1] = w1 * inv;
        sw[threadIdx.x][2] = w2 * inv;
        si[threadIdx.x][0] = i0;
        si[threadIdx.x][1] = i1;
        si[threadIdx.x][2] = i2;
    }
    __syncthreads();

    const float* g = g_gbuf + (long)b * NPTS1 * CF;
    const long mBase = (long)b * NPTS2 + p0;

    for (int e = threadIdx.x; e < 128 * 64; e += 256) {
        const int p = e >> 6;
        const int j = e & 63;
        const float w0 = sw[p][0], w1 = sw[p][1], w2 = sw[p][2];
        const float* r0 = g + (long)si[p][0] * CF + j * 8;
        const float* r1 = g + (long)si[p][1] * CF + j * 8;
        const float* r2 = g + (long)si[p][2] * CF + j * 8;
        float4 a0 = *(const float4*)r0, a1 = *(const float4*)(r0 + 4);
        float4 b0 = *(const float4*)r1, b1 = *(const float4*)(r1 + 4);
        float4 c0 = *(const float4*)r2, c1 = *(const float4*)(r2 + 4);

        float v[8];
        v[0] = w0 * a0.x + w1 * b0.x + w2 * c0.x;
        v[1] = w0 * a0.y + w1 * b0.y + w2 * c0.y;
        v[2] = w0 * a0.z + w1 * b0.z + w2 * c0.z;
        v[3] = w0 * a0.w + w1 * b0.w + w2 * c0.w;
        v[4] = w0 * a1.x + w1 * b1.x + w2 * c1.x;
        v[5] = w0 * a1.y + w1 * b1.y + w2 * c1.y;
        v[6] = w0 * a1.z + w1 * b1.z + w2 * c1.z;
        v[7] = w0 * a1.w + w1 * b1.w + w2 * c1.w;

        union { __nv_bfloat16 h[8]; uint4 u; } H, L;
#pragma unroll
        for (int k = 0; k < 8; k++) {
            float vr = fmaxf(v[k], 0.f);
            H.h[k] = __float2bfloat16(vr);
            L.h[k] = __float2bfloat16(vr - __bfloat162float(H.h[k]));
        }
        const long off = (mBase + p) * CF + j * 8;
        *(uint4*)(g_a2_hi + off) = H.u;
        *(uint4*)(g_a2_lo + off) = L.u;
    }
}

// ---------------------------------------------------------------- launch
extern "C" void kernel_launch(void* const* d_in, const int* in_sizes, int n_in,
                              void* d_out, int out_size)
{
    const float* xyz_dense  = (const float*)d_in[0];
    const float* xyz_sparse = (const float*)d_in[1];
    const float* feat       = (const float*)d_in[2];
    const float* W1         = (const float*)d_in[3];
    const float* b1         = (const float*)d_in[4];
    const float* W2         = (const float*)d_in[5];
    const float* b2         = (const float*)d_in[6];
    float* out = (float*)d_out;

    static bool attr_done = false;
    if (!attr_done) {
        cudaFuncSetAttribute(mma_gemm_kernel<0>,
            cudaFuncAttributeMaxDynamicSharedMemorySize, SMEM_GEMM);
        cudaFuncSetAttribute(mma_gemm_kernel<1>,
            cudaFuncAttributeMaxDynamicSharedMemorySize, SMEM_GEMM);
        attr_done = true;
    }

    convert_split_kernel<0><<<(16384 * 64) / 256, 256>>>(feat);
    convert_split_kernel<1><<<(512 * 64) / 256, 256>>>(W1);
    convert_split_kernel<2><<<(512 * 64) / 256, 256>>>(W2);

    {
        dim3 grid(4, MTILES1);
        mma_gemm_kernel<0><<<grid, 128, SMEM_GEMM>>>(b1, nullptr);
    }
    {
        dim3 grid(NPTS2 / 128, BB);
        knn_interp_relu_kernel<<<grid, 256>>>(xyz_dense, xyz_sparse);
    }
    {
        dim3 grid(4, MTILES2);
        mma_gemm_kernel<1><<<grid, 128, SMEM_GEMM>>>(b2, out);
    }
}

// round 10
// speedup vs baseline: 1.1238x; 1.1238x over previous
#include <cuda_runtime.h>
#include <cuda_bf16.h>
#include <math.h>
#include <stdint.h>

// ---------------------------------------------------------------- constants
#define BB    16
#define NPTS1 1024
#define NPTS2 4096
#define CF    512
#define EPSI  1e-10f

#define MTILES1 128            // 16384/128
#define MTILES2 512            // 65536/128
#define KITERS  16             // 512 / BK32

// SMEM tile geometry: per matrix 128 rows x 32 bf16 (64B data, padded to 80B)
#define ROW_STRIDE 80
#define MAT_BYTES  (128 * ROW_STRIDE)      // 10240
#define STAGE_BYTES (4 * MAT_BYTES)        // 40960 (Ahi|Alo|Bhi|Blo)
#define NSTAGES 2
#define SMEM_BARS (NSTAGES * STAGE_BYTES)  // 81920: full0,full1,empty0,empty1
#define SMEM_GEMM (SMEM_BARS + 64)

#define NTHREADS 288           // 8 consumer warps + 1 producer warp
#define NCONS    256

// ---------------------------------------------------------------- scratch
__device__ __align__(128) __nv_bfloat16 g_fA_hi[16384 * 512];
__device__ __align__(128) __nv_bfloat16 g_fA_lo[16384 * 512];
__device__ __align__(128) __nv_bfloat16 g_w1_hi[512 * 512];
__device__ __align__(128) __nv_bfloat16 g_w1_lo[512 * 512];
__device__ __align__(128) __nv_bfloat16 g_w2_hi[512 * 512];
__device__ __align__(128) __nv_bfloat16 g_w2_lo[512 * 512];
__device__ __align__(128) __nv_bfloat16 g_a2_hi[65536 * 512];
__device__ __align__(128) __nv_bfloat16 g_a2_lo[65536 * 512];
__device__ float g_gbuf[16384 * 512];   // GEMM1 output (fp32)

// ---------------------------------------------------------------- helpers
__device__ __forceinline__ uint32_t smem_u32(const void* p) {
    uint32_t a;
    asm("{ .reg .u64 t; cvta.to.shared.u64 t, %1; cvt.u32.u64 %0, t; }"
        : "=r"(a) : "l"(p));
    return a;
}

__device__ __forceinline__ void cp16(uint32_t dst, const void* src) {
    asm volatile("cp.async.cg.shared.global [%0], [%1], 16;" :: "r"(dst), "l"(src));
}

#define MBARRIER_INIT(addr, cnt) \
    asm volatile("mbarrier.init.shared.b64 [%0], %1;" :: "r"(addr), "r"((uint32_t)(cnt)) : "memory")

#define MBARRIER_ARRIVE(addr) \
    asm volatile("mbarrier.arrive.shared.b64 _, [%0];" :: "r"(addr) : "memory")

#define CP_ARRIVE_NOINC(addr) \
    asm volatile("cp.async.mbarrier.arrive.noinc.shared.b64 [%0];" :: "r"(addr) : "memory")

#define MBARRIER_WAIT_PARITY(addr, par) do {                                   \
    uint32_t _m = (addr); uint32_t _p = (uint32_t)(par); uint32_t _d;          \
    asm volatile("{\n\t.reg .pred p;\n\t"                                      \
        "mbarrier.try_wait.parity.acquire.cta.shared::cta.b64 p, [%1], %2;\n\t"\
        "selp.b32 %0, 1, 0, p;\n\t}"                                           \
        : "=r"(_d) : "r"(_m), "r"(_p) : "memory");                             \
    if (!_d) {                                                                 \
        asm volatile("{\n\t.reg .pred P1;\n\t"                                 \
            "W_%=:\n\t"                                                        \
            "mbarrier.try_wait.parity.acquire.cta.shared::cta.b64 P1, [%0], %1, 0x989680;\n\t" \
            "@P1 bra.uni D_%=;\n\t"                                            \
            "bra.uni W_%=;\n\t"                                                \
            "D_%=:\n\t}" :: "r"(_m), "r"(_p) : "memory");                      \
    }                                                                          \
} while (0)

#define LDSM_X4(r0_, r1_, r2_, r3_, addr_)                                    \
    asm volatile("ldmatrix.sync.aligned.m8n8.x4.shared.b16 {%0,%1,%2,%3}, [%4];" \
        : "=r"(r0_), "=r"(r1_), "=r"(r2_), "=r"(r3_) : "r"(addr_))

// D += A(16x16 bf16, row-major) * B(16x8 bf16, col-major), fp32 accum
#define MMA_BF16(d, a0_, a1_, a2_, a3_, b0_, b1_)                             \
    asm volatile("mma.sync.aligned.m16n8k16.row.col.f32.bf16.bf16.f32 "       \
        "{%0,%1,%2,%3}, {%4,%5,%6,%7}, {%8,%9}, {%0,%1,%2,%3};"               \
        : "+f"((d)[0]), "+f"((d)[1]), "+f"((d)[2]), "+f"((d)[3])              \
        : "r"(a0_), "r"(a1_), "r"(a2_), "r"(a3_), "r"(b0_), "r"(b1_))

// ---------------------------------------------------------------- converters
template <int WHICH>  // 0: feat->fA   1: W1->w1   2: W2->w2
__global__ __launch_bounds__(256) void convert_split_kernel(const float* __restrict__ src)
{
    __nv_bfloat16* dhi = (WHICH == 0) ? g_fA_hi : (WHICH == 1) ? g_w1_hi : g_w2_hi;
    __nv_bfloat16* dlo = (WHICH == 0) ? g_fA_lo : (WHICH == 1) ? g_w1_lo : g_w2_lo;

    const long t = (long)blockIdx.x * 256 + threadIdx.x;
    const float4* s = (const float4*)(src + t * 8);
    float4 v0 = s[0], v1 = s[1];
    float v[8] = { v0.x, v0.y, v0.z, v0.w, v1.x, v1.y, v1.z, v1.w };

    union { __nv_bfloat16 h[8]; uint4 u; } H, L;
#pragma unroll
    for (int k = 0; k < 8; k++) {
        H.h[k] = __float2bfloat16(v[k]);
        L.h[k] = __float2bfloat16(v[k] - __bfloat162float(H.h[k]));
    }
    *(uint4*)(dhi + t * 8) = H.u;
    *(uint4*)(dlo + t * 8) = L.u;
}

// ---------------------------------------------------------------- MMA GEMM
// C[M,512] = A[M,512] @ W[512,512]^T + bias, 3-term bf16 split:
//   AhiBhi + AhiBlo + AloBhi  (AloBlo dropped, ~2^-18)
// Warp-specialized: warps 0-7 consume (32x64 warp tiles), warp 8 produces
// (cp.async). mbarrier full/empty per stage; NO __syncthreads in mainloop.
// MODE 0: A = fA (feat), B = w1, C = g_gbuf.  MODE 1: A = a2, B = w2, C = param.
template <int MODE>
__global__ __launch_bounds__(NTHREADS, 2) void mma_gemm_kernel(const float* __restrict__ bias,
                                                               float* __restrict__ Cout)
{
    extern __shared__ __align__(128) char smem[];
    const uint32_t sbase = smem_u32(smem);
    const uint32_t fullB  = sbase + SMEM_BARS;      // full0, full1
    const uint32_t emptyB = fullB + 16;             // empty0, empty1

    const int tid  = threadIdx.x;
    const int wid  = tid >> 5, lane = tid & 31;
    const int ntile = blockIdx.x, mtile = blockIdx.y;

    const __nv_bfloat16* Ahi = (MODE == 0) ? g_fA_hi : g_a2_hi;
    const __nv_bfloat16* Alo = (MODE == 0) ? g_fA_lo : g_a2_lo;
    const __nv_bfloat16* Bhi = (MODE == 0) ? g_w1_hi : g_w2_hi;
    const __nv_bfloat16* Blo = (MODE == 0) ? g_w1_lo : g_w2_lo;

    if (tid == 0) {
        MBARRIER_INIT(fullB + 0,  32);   // producer-warp cp.async completions
        MBARRIER_INIT(fullB + 8,  32);
        MBARRIER_INIT(emptyB + 0, NCONS);
        MBARRIER_INIT(emptyB + 8, NCONS);
        asm volatile("fence.proxy.async.shared::cta;" ::: "memory");
    }
    __syncthreads();   // only sync in the kernel

    if (wid == 8) {
        // ------------------------------------------------ producer warp
        const char* gbase[4];
        gbase[0] = (const char*)(Ahi + (long)mtile * 128 * 512);
        gbase[1] = (const char*)(Alo + (long)mtile * 128 * 512);
        gbase[2] = (const char*)(Bhi + (long)ntile * 128 * 512);
        gbase[3] = (const char*)(Blo + (long)ntile * 128 * 512);

        // each of 32 threads copies 64 x 16B per stage (2048 total)
        auto produce = [&](int kc, int s) {
            const uint32_t stg = sbase + s * STAGE_BYTES;
#pragma unroll
            for (int mat = 0; mat < 4; mat++) {
#pragma unroll
                for (int j = 0; j < 16; j++) {
                    const int rem = j * 32 + lane;     // 0..511
                    const int row = rem >> 2, chk = rem & 3;
                    cp16(stg + mat * MAT_BYTES + row * ROW_STRIDE + chk * 16,
                         gbase[mat] + (long)row * 1024 + kc * 64 + chk * 16);
                }
            }
            CP_ARRIVE_NOINC(fullB + s * 8);
        };

        produce(0, 0);
        produce(1, 1);
        for (int kt = 2; kt < KITERS; kt++) {
            const int s = kt & 1, u = kt >> 1;
            MBARRIER_WAIT_PARITY(emptyB + s * 8, (u - 1) & 1);
            produce(kt, s);
        }
        return;
    }

    // ---------------------------------------------------- consumer warps
    const int warp_m = wid & 3;     // 0..3 -> 32-row strip
    const int warp_n = wid >> 2;    // 0..1 -> 64-col strip
    const int qid = lane >> 2;
    const int qtr = lane & 3;

    float acc[2][8][4];
#pragma unroll
    for (int mt = 0; mt < 2; mt++)
#pragma unroll
        for (int nt = 0; nt < 8; nt++)
#pragma unroll
            for (int i = 0; i < 4; i++) acc[mt][nt][i] = 0.f;

    const uint32_t lrow = lane & 15;
    const uint32_t lcolB = (lane >> 4) * 16;
    const uint32_t aoff0 = (warp_m * 32 + 0  + lrow) * ROW_STRIDE + lcolB;
    const uint32_t aoff1 = (warp_m * 32 + 16 + lrow) * ROW_STRIDE + lcolB;
    uint32_t boff[4];
#pragma unroll
    for (int ntp = 0; ntp < 4; ntp++)
        boff[ntp] = (warp_n * 64 + ntp * 16 + lrow) * ROW_STRIDE + lcolB;

    for (int kt = 0; kt < KITERS; kt++) {
        const int s = kt & 1, u = kt >> 1;
        MBARRIER_WAIT_PARITY(fullB + s * 8, u & 1);

        const uint32_t aHiB = sbase + s * STAGE_BYTES;
        const uint32_t aLoB = aHiB + MAT_BYTES;
        const uint32_t bHiB = aHiB + 2 * MAT_BYTES;
        const uint32_t bLoB = aHiB + 3 * MAT_BYTES;
#pragma unroll
        for (int ks = 0; ks < 2; ks++) {
            const uint32_t ko = ks * 32;
            uint32_t ah0[4], ah1[4], al0[4], al1[4];
            LDSM_X4(ah0[0], ah0[1], ah0[2], ah0[3], aHiB + aoff0 + ko);
            LDSM_X4(ah1[0], ah1[1], ah1[2], ah1[3], aHiB + aoff1 + ko);
            LDSM_X4(al0[0], al0[1], al0[2], al0[3], aLoB + aoff0 + ko);
            LDSM_X4(al1[0], al1[1], al1[2], al1[3], aLoB + aoff1 + ko);
            uint32_t bh[4][4], bl[4][4];
#pragma unroll
            for (int ntp = 0; ntp < 4; ntp++) {
                LDSM_X4(bh[ntp][0], bh[ntp][1], bh[ntp][2], bh[ntp][3], bHiB + boff[ntp] + ko);
                LDSM_X4(bl[ntp][0], bl[ntp][1], bl[ntp][2], bl[ntp][3], bLoB + boff[ntp] + ko);
            }
            // term 1: Ahi * Bhi
#pragma unroll
            for (int ntp = 0; ntp < 4; ntp++) {
                MMA_BF16(acc[0][2*ntp],   ah0[0],ah0[1],ah0[2],ah0[3], bh[ntp][0], bh[ntp][2]);
                MMA_BF16(acc[1][2*ntp],   ah1[0],ah1[1],ah1[2],ah1[3], bh[ntp][0], bh[ntp][2]);
                MMA_BF16(acc[0][2*ntp+1], ah0[0],ah0[1],ah0[2],ah0[3], bh[ntp][1], bh[ntp][3]);
                MMA_BF16(acc[1][2*ntp+1], ah1[0],ah1[1],ah1[2],ah1[3], bh[ntp][1], bh[ntp][3]);
            }
            // term 2: Ahi * Blo
#pragma unroll
            for (int ntp = 0; ntp < 4; ntp++) {
                MMA_BF16(acc[0][2*ntp],   ah0[0],ah0[1],ah0[2],ah0[3], bl[ntp][0], bl[ntp][2]);
                MMA_BF16(acc[1][2*ntp],   ah1[0],ah1[1],ah1[2],ah1[3], bl[ntp][0], bl[ntp][2]);
                MMA_BF16(acc[0][2*ntp+1], ah0[0],ah0[1],ah0[2],ah0[3], bl[ntp][1], bl[ntp][3]);
                MMA_BF16(acc[1][2*ntp+1], ah1[0],ah1[1],ah1[2],ah1[3], bl[ntp][1], bl[ntp][3]);
            }
            // term 3: Alo * Bhi
#pragma unroll
            for (int ntp = 0; ntp < 4; ntp++) {
                MMA_BF16(acc[0][2*ntp],   al0[0],al0[1],al0[2],al0[3], bh[ntp][0], bh[ntp][2]);
                MMA_BF16(acc[1][2*ntp],   al1[0],al1[1],al1[2],al1[3], bh[ntp][0], bh[ntp][2]);
                MMA_BF16(acc[0][2*ntp+1], al0[0],al0[1],al0[2],al0[3], bh[ntp][1], bh[ntp][3]);
                MMA_BF16(acc[1][2*ntp+1], al1[0],al1[1],al1[2],al1[3], bh[ntp][1], bh[ntp][3]);
            }
        }
        MBARRIER_ARRIVE(emptyB + s * 8);
    }

    // ---- epilogue: +bias, direct float2 stores
    float* Cbase = (MODE == 0) ? g_gbuf : Cout;
#pragma unroll
    for (int mt = 0; mt < 2; mt++) {
        const int r0 = mtile * 128 + warp_m * 32 + mt * 16 + qid;
#pragma unroll
        for (int nt = 0; nt < 8; nt++) {
            const int col = ntile * 128 + warp_n * 64 + nt * 8 + qtr * 2;
            const float b0 = __ldg(&bias[col]), b1 = __ldg(&bias[col + 1]);
            float2 v0, v1;
            v0.x = acc[mt][nt][0] + b0; v0.y = acc[mt][nt][1] + b1;
            v1.x = acc[mt][nt][2] + b0; v1.y = acc[mt][nt][3] + b1;
            *(float2*)&Cbase[(long)r0 * 512 + col] = v0;
            *(float2*)&Cbase[(long)(r0 + 8) * 512 + col] = v1;
        }
    }
}

// ---------------------------------------------------------------- KNN + interp
__global__ __launch_bounds__(256) void knn_interp_relu_kernel(
    const float* __restrict__ xyz_dense, const float* __restrict__ xyz_sparse)
{
    __shared__ float sx[NPTS1], sy[NPTS1], sz[NPTS1];
    __shared__ float sw[128][3];
    __shared__ int   si[128][3];

    const int b  = blockIdx.y;
    const int p0 = blockIdx.x * 128;

    const float* xs = xyz_sparse + (long)b * NPTS1 * 3;
    for (int i = threadIdx.x; i < NPTS1; i += 256) {
        sx[i] = xs[i * 3 + 0];
        sy[i] = xs[i * 3 + 1];
        sz[i] = xs[i * 3 + 2];
    }
    __syncthreads();

    if (threadIdx.x < 128) {
        const int p = p0 + threadIdx.x;
        const float* xd = xyz_dense + ((long)b * NPTS2 + p) * 3;
        const float px = xd[0], py = xd[1], pz = xd[2];

        float d0 = 1e30f, d1 = 1e30f, d2 = 1e30f;
        int   i0 = 0, i1 = 0, i2 = 0;
#pragma unroll 4
        for (int j = 0; j < NPTS1; j++) {
            float dx = px - sx[j], dy = py - sy[j], dz = pz - sz[j];
            float d = dx * dx + dy * dy + dz * dz;
            if (d < d0)      { d2 = d1; i2 = i1; d1 = d0; i1 = i0; d0 = d; i0 = j; }
            else if (d < d1) { d2 = d1; i2 = i1; d1 = d;  i1 = j; }
            else if (d < d2) { d2 = d;  i2 = j; }
        }
        float w0 = 1.f / (sqrtf(d0) + EPSI);
        float w1 = 1.f / (sqrtf(d1) + EPSI);
        float w2 = 1.f / (sqrtf(d2) + EPSI);
        const float inv = 1.f / (w0 + w1 + w2);
        sw[threadIdx.x][0] = w0 * inv;
        sw[threadIdx.x][1] = w1 * inv;
        sw[threadIdx.x][2] = w2 * inv;
        si[threadIdx.x][0] = i0;
        si[threadIdx.x][1] = i1;
        si[threadIdx.x][2] = i2;
    }
    __syncthreads();

    const float* g = g_gbuf + (long)b * NPTS1 * CF;
    const long mBase = (long)b * NPTS2 + p0;

    for (int e = threadIdx.x; e < 128 * 64; e += 256) {
        const int p = e >> 6;
        const int j = e & 63;
        const float w0 = sw[p][0], w1 = sw[p][1], w2 = sw[p][2];
        const float* r0 = g + (long)si[p][0] * CF + j * 8;
        const float* r1 = g + (long)si[p][1] * CF + j * 8;
        const float* r2 = g + (long)si[p][2] * CF + j * 8;
        float4 a0 = *(const float4*)r0, a1 = *(const float4*)(r0 + 4);
        float4 b0 = *(const float4*)r1, b1 = *(const float4*)(r1 + 4);
        float4 c0 = *(const float4*)r2, c1 = *(const float4*)(r2 + 4);

        float v[8];
        v[0] = w0 * a0.x + w1 * b0.x + w2 * c0.x;
        v[1] = w0 * a0.y + w1 * b0.y + w2 * c0.y;
        v[2] = w0 * a0.z + w1 * b0.z + w2 * c0.z;
        v[3] = w0 * a0.w + w1 * b0.w + w2 * c0.w;
        v[4] = w0 * a1.x + w1 * b1.x + w2 * c1.x;
        v[5] = w0 * a1.y + w1 * b1.y + w2 * c1.y;
        v[6] = w0 * a1.z + w1 * b1.z + w2 * c1.z;
        v[7] = w0 * a1.w + w1 * b1.w + w2 * c1.w;

        union { __nv_bfloat16 h[8]; uint4 u; } H, L;
#pragma unroll
        for (int k = 0; k < 8; k++) {
            float vr = fmaxf(v[k], 0.f);
            H.h[k] = __float2bfloat16(vr);
            L.h[k] = __float2bfloat16(vr - __bfloat162float(H.h[k]));
        }
        const long off = (mBase + p) * CF + j * 8;
        *(uint4*)(g_a2_hi + off) = H.u;
        *(uint4*)(g_a2_lo + off) = L.u;
    }
}

// ---------------------------------------------------------------- launch
extern "C" void kernel_launch(void* const* d_in, const int* in_sizes, int n_in,
                              void* d_out, int out_size)
{
    const float* xyz_dense  = (const float*)d_in[0];
    const float* xyz_sparse = (const float*)d_in[1];
    const float* feat       = (const float*)d_in[2];
    const float* W1         = (const float*)d_in[3];
    const float* b1         = (const float*)d_in[4];
    const float* W2         = (const float*)d_in[5];
    const float* b2         = (const float*)d_in[6];
    float* out = (float*)d_out;

    static bool attr_done = false;
    if (!attr_done) {
        cudaFuncSetAttribute(mma_gemm_kernel<0>,
            cudaFuncAttributeMaxDynamicSharedMemorySize, SMEM_GEMM);
        cudaFuncSetAttribute(mma_gemm_kernel<1>,
            cudaFuncAttributeMaxDynamicSharedMemorySize, SMEM_GEMM);
        attr_done = true;
    }

    convert_split_kernel<0><<<(16384 * 64) / 256, 256>>>(feat);
    convert_split_kernel<1><<<(512 * 64) / 256, 256>>>(W1);
    convert_split_kernel<2><<<(512 * 64) / 256, 256>>>(W2);

    {
        dim3 grid(4, MTILES1);
        mma_gemm_kernel<0><<<grid, NTHREADS, SMEM_GEMM>>>(b1, nullptr);
    }
    {
        dim3 grid(NPTS2 / 128, BB);
        knn_interp_relu_kernel<<<grid, 256>>>(xyz_dense, xyz_sparse);
    }
    {
        dim3 grid(4, MTILES2);
        mma_gemm_kernel<1><<<grid, NTHREADS, SMEM_GEMM>>>(b2, out);
    }
}